// round 3
// baseline (speedup 1.0000x reference)
#include <cuda_runtime.h>
#include <cuda_bf16.h>
#include <cstddef>

// Problem constants
#define BATCH 2
#define SEQ   2048
#define DIM   1024
#define NHEAD 16
#define HDIM  64
#define M_ROWS (BATCH * SEQ)   // 4096

// Scratch (device globals; no allocation allowed)
__device__ float g_q[(size_t)M_ROWS * DIM];        // 16 MB
__device__ float g_kv[(size_t)M_ROWS * 2 * DIM];   // 32 MB
__device__ float g_y[(size_t)M_ROWS * DIM];        // 16 MB

// ---------------------------------------------------------------------------
// SGEMM: C[M,N] = A[M,K] @ B[K,N], fp32, all dims divisible by tile sizes.
// 128x128 block tile, BK=8, 256 threads, 8x8 per thread.
// ---------------------------------------------------------------------------
__global__ __launch_bounds__(256) void sgemm128(
    const float* __restrict__ A, const float* __restrict__ B,
    float* __restrict__ C, int M, int N, int K)
{
    __shared__ float As[8][128];
    __shared__ float Bs[8][128];

    const int tid = threadIdx.x;
    const int bRow = blockIdx.y * 128;
    const int bCol = blockIdx.x * 128;
    const int tx = tid & 15;        // 0..15
    const int ty = tid >> 4;        // 0..15

    // A tile load mapping: 128 rows x 8 cols, one float4 per thread
    const int aRow = tid >> 1;          // 0..127
    const int aCol = (tid & 1) * 4;     // 0 or 4
    // B tile load mapping: 8 rows x 128 cols, one float4 per thread
    const int bRowL = tid >> 5;         // 0..7
    const int bColL = (tid & 31) * 4;   // 0..124

    const float* Ap = A + (size_t)(bRow + aRow) * K + aCol;
    const float* Bp = B + (size_t)bRowL * N + bCol + bColL;

    float acc[8][8];
#pragma unroll
    for (int i = 0; i < 8; i++)
#pragma unroll
        for (int j = 0; j < 8; j++) acc[i][j] = 0.0f;

    for (int k0 = 0; k0 < K; k0 += 8) {
        float4 av = *(const float4*)(Ap + k0);
        As[aCol + 0][aRow] = av.x;
        As[aCol + 1][aRow] = av.y;
        As[aCol + 2][aRow] = av.z;
        As[aCol + 3][aRow] = av.w;
        float4 bv = *(const float4*)(Bp + (size_t)k0 * N);
        *(float4*)&Bs[bRowL][bColL] = bv;
        __syncthreads();

#pragma unroll
        for (int kk = 0; kk < 8; ++kk) {
            float4 a0 = *(const float4*)&As[kk][ty * 8];
            float4 a1 = *(const float4*)&As[kk][ty * 8 + 4];
            float4 b0 = *(const float4*)&Bs[kk][tx * 8];
            float4 b1 = *(const float4*)&Bs[kk][tx * 8 + 4];
            float ar[8] = {a0.x, a0.y, a0.z, a0.w, a1.x, a1.y, a1.z, a1.w};
            float br[8] = {b0.x, b0.y, b0.z, b0.w, b1.x, b1.y, b1.z, b1.w};
#pragma unroll
            for (int i = 0; i < 8; i++)
#pragma unroll
                for (int j = 0; j < 8; j++)
                    acc[i][j] = fmaf(ar[i], br[j], acc[i][j]);
        }
        __syncthreads();
    }

#pragma unroll
    for (int i = 0; i < 8; i++) {
        float* crow = C + (size_t)(bRow + ty * 8 + i) * N + bCol + tx * 8;
#pragma unroll
        for (int j = 0; j < 8; j += 4) {
            float4 v = make_float4(acc[i][j], acc[i][j + 1], acc[i][j + 2], acc[i][j + 3]);
            *(float4*)(crow + j) = v;
        }
    }
}

// ---------------------------------------------------------------------------
// Flash attention (fp32, online softmax).
// Grid: x = query block (T/64 = 32), y = b*NHEAD + h (32). 256 threads.
// Q tile 64x64, K/V tiles 32x64. Accumulator 4x4 per thread.
// q layout: [B,T,D] with head h at column offset h*64.
// kv layout: [B,T,2D]; k at col h*64, v at col 1024 + h*64.
// ---------------------------------------------------------------------------
__global__ __launch_bounds__(256) void attn_kernel(
    const float* __restrict__ q, const float* __restrict__ kv,
    float* __restrict__ y)
{
    const int qb = blockIdx.x;              // 0..31
    const int bh = blockIdx.y;
    const int b = bh / NHEAD;
    const int h = bh % NHEAD;
    const int tid = threadIdx.x;
    const int tx = tid & 15;
    const int ty = tid >> 4;

    __shared__ float Qs[64][65];
    __shared__ float Ks[32][65];
    __shared__ float Vs[32][65];
    __shared__ float Ss[64][33];
    __shared__ float mrow[64], lrow[64], frow[64];

    const float* qbase = q + ((size_t)b * SEQ + qb * 64) * DIM + h * HDIM;
    // Load + pre-scale Q by 1/sqrt(64)
    for (int i = tid; i < 64 * 64; i += 256) {
        int r = i >> 6, d = i & 63;
        Qs[r][d] = qbase[(size_t)r * DIM + d] * 0.125f;
    }
    if (tid < 64) { mrow[tid] = -1e30f; lrow[tid] = 0.0f; }

    float acc[4][4];
#pragma unroll
    for (int i = 0; i < 4; i++)
#pragma unroll
        for (int j = 0; j < 4; j++) acc[i][j] = 0.0f;

    const float* kbase = kv + (size_t)b * SEQ * (2 * DIM) + h * HDIM;
    const float* vbase = kbase + DIM;
    __syncthreads();

    for (int kb = 0; kb < SEQ; kb += 32) {
        // Load K, V tiles (coalesced along d)
        for (int i = tid; i < 32 * 64; i += 256) {
            int r = i >> 6, d = i & 63;
            size_t off = (size_t)(kb + r) * (2 * DIM) + d;
            Ks[r][d] = kbase[off];
            Vs[r][d] = vbase[off];
        }
        __syncthreads();

        // S = Q K^T : each thread rows ty*4..+3, cols tx*2..+1
        float s[4][2] = {{0.f, 0.f}, {0.f, 0.f}, {0.f, 0.f}, {0.f, 0.f}};
#pragma unroll
        for (int d = 0; d < 64; d++) {
            float k0 = Ks[tx * 2][d];
            float k1 = Ks[tx * 2 + 1][d];
#pragma unroll
            for (int i = 0; i < 4; i++) {
                float qv = Qs[ty * 4 + i][d];
                s[i][0] = fmaf(qv, k0, s[i][0]);
                s[i][1] = fmaf(qv, k1, s[i][1]);
            }
        }
#pragma unroll
        for (int i = 0; i < 4; i++) {
            Ss[ty * 4 + i][tx * 2] = s[i][0];
            Ss[ty * 4 + i][tx * 2 + 1] = s[i][1];
        }
        __syncthreads();

        // Online softmax per row (64 rows, 1 thread each)
        if (tid < 64) {
            float m_old = mrow[tid];
            float tm = m_old;
#pragma unroll
            for (int j = 0; j < 32; j++) tm = fmaxf(tm, Ss[tid][j]);
            float fac = __expf(m_old - tm);
            float sum = 0.0f;
#pragma unroll
            for (int j = 0; j < 32; j++) {
                float p = __expf(Ss[tid][j] - tm);
                Ss[tid][j] = p;
                sum += p;
            }
            mrow[tid] = tm;
            frow[tid] = fac;
            lrow[tid] = lrow[tid] * fac + sum;
        }
        __syncthreads();

        // Rescale accumulator, then O += P @ V (rows ty*4..+3, cols tx*4..+3)
#pragma unroll
        for (int i = 0; i < 4; i++) {
            float fr = frow[ty * 4 + i];
#pragma unroll
            for (int j = 0; j < 4; j++) acc[i][j] *= fr;
        }
#pragma unroll
        for (int kk = 0; kk < 32; kk++) {
            float pv[4], vv[4];
#pragma unroll
            for (int i = 0; i < 4; i++) pv[i] = Ss[ty * 4 + i][kk];
#pragma unroll
            for (int j = 0; j < 4; j++) vv[j] = Vs[kk][tx * 4 + j];
#pragma unroll
            for (int i = 0; i < 4; i++)
#pragma unroll
                for (int j = 0; j < 4; j++)
                    acc[i][j] = fmaf(pv[i], vv[j], acc[i][j]);
        }
        __syncthreads();
    }

    float* ybase = y + ((size_t)b * SEQ + qb * 64) * DIM + h * HDIM;
#pragma unroll
    for (int i = 0; i < 4; i++) {
        float inv = 1.0f / lrow[ty * 4 + i];
#pragma unroll
        for (int j = 0; j < 4; j++)
            ybase[(size_t)(ty * 4 + i) * DIM + tx * 4 + j] = acc[i][j] * inv;
    }
}

// ---------------------------------------------------------------------------
// Launch
// Inputs (metadata order): x [B,T,D], e [B,T,D], W_en [D,2D], W_q [D,D], W_o [D,D]
// Output: [B,T,D] fp32
// ---------------------------------------------------------------------------
extern "C" void kernel_launch(void* const* d_in, const int* in_sizes, int n_in,
                              void* d_out, int out_size)
{
    const float* x    = (const float*)d_in[0];
    const float* e    = (const float*)d_in[1];
    const float* W_en = (const float*)d_in[2];
    const float* W_q  = (const float*)d_in[3];
    const float* W_o  = (const float*)d_in[4];
    float* out = (float*)d_out;

    float *qp, *kvp, *yp;
    cudaGetSymbolAddress((void**)&qp, g_q);
    cudaGetSymbolAddress((void**)&kvp, g_kv);
    cudaGetSymbolAddress((void**)&yp, g_y);

    // q = x @ W_q : [4096,1024] @ [1024,1024]
    {
        dim3 grid(DIM / 128, M_ROWS / 128);
        sgemm128<<<grid, 256>>>(x, W_q, qp, M_ROWS, DIM, DIM);
    }
    // kv = e @ W_en : [4096,1024] @ [1024,2048]
    {
        dim3 grid((2 * DIM) / 128, M_ROWS / 128);
        sgemm128<<<grid, 256>>>(e, W_en, kvp, M_ROWS, 2 * DIM, DIM);
    }
    // attention -> y
    {
        dim3 grid(SEQ / 64, BATCH * NHEAD);
        attn_kernel<<<grid, 256>>>(qp, kvp, yp);
    }
    // out = y @ W_o : [4096,1024] @ [1024,1024]
    {
        dim3 grid(DIM / 128, M_ROWS / 128);
        sgemm128<<<grid, 256>>>(yp, W_o, out, M_ROWS, DIM, DIM);
    }
}